// round 15
// baseline (speedup 1.0000x reference)
#include <cuda_runtime.h>
#include <math.h>

// Problem constants
#define Bc   4
#define Nc   2048
#define INc  128
#define OUTc 64
#define Hc   4
#define HKc  256   // H * OUT

// ---------------------------------------------------------------------------
// Scratch (device globals — allocation-free rule)
// ---------------------------------------------------------------------------
__device__ float g_phi[Bc * Nc * 128];           //  4 MB  [row][128] cos|sin
__device__ float g_Q  [Bc * Nc * 64];            //  2 MB
__device__ float g_K  [Bc * Nc * 64];            //  2 MB
__device__ float g_Wh [Bc * Nc * 256];           //  8 MB
__device__ float g_S  [(size_t)Bc * Nc * Nc];    // 64 MB  pre-softmax scores

// ---------------------------------------------------------------------------
// Kernel 1 family: row GEMMs  Y(8192 x OUTW) = X(8192 x 128) @ W(128 x OUTW)
// MODE 0: X=h,   W=random_projection (OUTW=64)  -> g_phi = [cos, sin]
// MODE 1: X=g_phi, W=[a_q | a_k]     (OUTW=128) -> g_Q, g_K
// MODE 2: X=h,   W=W                 (OUTW=256) -> g_Wh
// 256 threads: ty=t/16 -> 4 rows, tx=t%16 -> OUTW/16 cols. Weights + X in smem.
// ---------------------------------------------------------------------------
template<int OUTW, int MODE>
__global__ __launch_bounds__(256)
void rowgemm_kernel(const float* __restrict__ X,
                    const float* __restrict__ W0,
                    const float* __restrict__ W1)
{
    constexpr int CW = OUTW / 16;
    extern __shared__ float smem[];
    float* Ws = smem;                 // 128 * OUTW
    float* Xs = smem + 128 * OUTW;    // 64 * 132 (padded)

    const int tid  = threadIdx.x;
    const int row0 = blockIdx.x * 64;

    // Stage weights
    if constexpr (MODE == 1) {
        for (int idx = tid * 4; idx < 128 * 64; idx += 1024) {
            int d = idx >> 6, o = idx & 63;
            *(float4*)(Ws + d * 128 + o)      = *(const float4*)(W0 + idx);
            *(float4*)(Ws + d * 128 + 64 + o) = *(const float4*)(W1 + idx);
        }
    } else {
        for (int idx = tid * 4; idx < 128 * OUTW; idx += 1024)
            *(float4*)(Ws + idx) = *(const float4*)(W0 + idx);
    }
    // Stage X tile (64 x 128, padded stride 132)
    const float* Xp = (MODE == 1) ? (const float*)g_phi : X;
    for (int idx = tid * 4; idx < 64 * 128; idx += 1024) {
        int rl = idx >> 7, d = idx & 127;
        *(float4*)(Xs + rl * 132 + d) =
            *(const float4*)(Xp + (size_t)(row0 + rl) * 128 + d);
    }
    __syncthreads();

    const int ty = tid >> 4, tx = tid & 15;
    float acc[4][CW];
    #pragma unroll
    for (int r = 0; r < 4; r++)
        #pragma unroll
        for (int c = 0; c < CW; c++) acc[r][c] = 0.f;

    for (int d = 0; d < 128; d++) {
        float xv[4];
        #pragma unroll
        for (int r = 0; r < 4; r++) xv[r] = Xs[(ty * 4 + r) * 132 + d];
        #pragma unroll
        for (int c4 = 0; c4 < CW; c4 += 4) {
            float4 w = *(float4*)(Ws + d * OUTW + tx * CW + c4);
            #pragma unroll
            for (int r = 0; r < 4; r++) {
                acc[r][c4 + 0] += xv[r] * w.x;
                acc[r][c4 + 1] += xv[r] * w.y;
                acc[r][c4 + 2] += xv[r] * w.z;
                acc[r][c4 + 3] += xv[r] * w.w;
            }
        }
    }

    #pragma unroll
    for (int r = 0; r < 4; r++) {
        int row = row0 + ty * 4 + r;
        if constexpr (MODE == 0) {
            // phi = [cos(proj), sin(proj)]
            float4 cv = make_float4(cosf(acc[r][0]), cosf(acc[r][1]),
                                    cosf(acc[r][2]), cosf(acc[r][3]));
            float4 sv = make_float4(sinf(acc[r][0]), sinf(acc[r][1]),
                                    sinf(acc[r][2]), sinf(acc[r][3]));
            *(float4*)(g_phi + (size_t)row * 128 + tx * 4)      = cv;
            *(float4*)(g_phi + (size_t)row * 128 + 64 + tx * 4) = sv;
        } else if constexpr (MODE == 1) {
            #pragma unroll
            for (int c4 = 0; c4 < CW; c4 += 4) {
                float4 v = make_float4(acc[r][c4], acc[r][c4 + 1],
                                       acc[r][c4 + 2], acc[r][c4 + 3]);
                int o = tx * CW + c4;
                if (o < 64) *(float4*)(g_Q + (size_t)row * 64 + o)        = v;
                else        *(float4*)(g_K + (size_t)row * 64 + (o - 64)) = v;
            }
        } else {
            #pragma unroll
            for (int c4 = 0; c4 < CW; c4 += 4) {
                float4 v = make_float4(acc[r][c4], acc[r][c4 + 1],
                                       acc[r][c4 + 2], acc[r][c4 + 3]);
                *(float4*)(g_Wh + (size_t)row * 256 + tx * CW + c4) = v;
            }
        }
    }
}

// ---------------------------------------------------------------------------
// Kernel 2: pre-softmax scores
//   g_S[b,i,j] = Q[b,i]·K[b,j] + P[b,i,j] + Sim[b,i,j] + qbias[qm0, qm1]
// CTA tile 64i x 64j, thread tile 4x4. Memory-bound (streams P/Sim/qm).
// ---------------------------------------------------------------------------
__global__ __launch_bounds__(256)
void scores_kernel(const float* __restrict__ P, const float* __restrict__ Sim,
                   const int* __restrict__ qm, const float* __restrict__ qbias)
{
    __shared__ float Qs[64 * 65];
    __shared__ float Kst[64 * 65];   // transposed: [d][jl]
    __shared__ float qbs[16];

    const int b = blockIdx.z, i0 = blockIdx.y * 64, j0 = blockIdx.x * 64;
    const int tid = threadIdx.x;
    const int bn = b * Nc;

    if (tid < 16) qbs[tid] = qbias[tid];
    for (int idx = tid; idx < 4096; idx += 256) {
        int il = idx >> 6, d = idx & 63;
        Qs[il * 65 + d] = g_Q[(size_t)(bn + i0 + il) * 64 + d];
    }
    for (int idx = tid; idx < 4096; idx += 256) {
        int jl = idx >> 6, d = idx & 63;
        Kst[d * 65 + jl] = g_K[(size_t)(bn + j0 + jl) * 64 + d];
    }
    __syncthreads();

    const int ty = tid >> 4, tx = tid & 15;
    float acc[4][4];
    #pragma unroll
    for (int r = 0; r < 4; r++)
        #pragma unroll
        for (int c = 0; c < 4; c++) acc[r][c] = 0.f;

    #pragma unroll 4
    for (int d = 0; d < 64; d++) {
        float qv[4], kv[4];
        #pragma unroll
        for (int r = 0; r < 4; r++) qv[r] = Qs[(ty * 4 + r) * 65 + d];
        #pragma unroll
        for (int c = 0; c < 4; c++) kv[c] = Kst[d * 65 + tx * 4 + c];
        #pragma unroll
        for (int r = 0; r < 4; r++)
            #pragma unroll
            for (int c = 0; c < 4; c++) acc[r][c] += qv[r] * kv[c];
    }

    #pragma unroll
    for (int r = 0; r < 4; r++) {
        int i = i0 + ty * 4 + r;
        size_t gi = (size_t)(bn + i) * Nc + j0 + tx * 4;
        float4 p4 = *(const float4*)(P + gi);
        float4 s4 = *(const float4*)(Sim + gi);
        int4 qa = *(const int4*)(qm + gi * 2);
        int4 qb = *(const int4*)(qm + gi * 2 + 4);
        float4 o;
        o.x = acc[r][0] + p4.x + s4.x + qbs[qa.x * 4 + qa.y];
        o.y = acc[r][1] + p4.y + s4.y + qbs[qa.z * 4 + qa.w];
        o.z = acc[r][2] + p4.z + s4.z + qbs[qb.x * 4 + qb.y];
        o.w = acc[r][3] + p4.w + s4.w + qbs[qb.z * 4 + qb.w];
        *(float4*)(g_S + gi) = o;
    }
}

// ---------------------------------------------------------------------------
// Kernel 3: fused online-softmax + attn@Wh + output projection + elu
// One CTA per (b, 64-query tile). 256 threads: ty=t/16 -> 4 rows,
// tx=t%16 -> 16 of 256 hp columns (acc[4][16] registers).
// Softmax phase uses (row = t/4, q = t%4) with intra-quad shuffles.
// ---------------------------------------------------------------------------
__global__ __launch_bounds__(256)
void attn_kernel(const float* __restrict__ Wproj, float* __restrict__ out)
{
    extern __shared__ float smem[];
    float* sp   = smem;                 // 64 * 68  (scores -> probs)
    float* whs  = smem + 64 * 68;       // 64 * 260 (Wh tile, later hp tile)
    float* m_s  = whs + 64 * 260;       // 64
    float* l_s  = m_s + 64;             // 64
    float* sc_s = l_s + 64;             // 64

    const int b  = blockIdx.y;
    const int i0 = blockIdx.x * 64;
    const int tid = threadIdx.x;
    const int ty = tid >> 4, tx = tid & 15;
    const int row = tid >> 2, q = tid & 3;
    const int bn = b * Nc;

    float acc[4][16];
    #pragma unroll
    for (int r = 0; r < 4; r++)
        #pragma unroll
        for (int c = 0; c < 16; c++) acc[r][c] = 0.f;

    if (tid < 64) { m_s[tid] = -1e30f; l_s[tid] = 0.f; }

    for (int jt = 0; jt < 32; jt++) {
        const int j0 = jt * 64;
        // load score tile (64 x 64)
        for (int idx = tid * 4; idx < 4096; idx += 1024) {
            int il = idx >> 6, jl = idx & 63;
            *(float4*)(sp + il * 68 + jl) =
                *(const float4*)(g_S + (size_t)(bn + i0 + il) * Nc + j0 + jl);
        }
        // load Wh tile (64 x 256)
        for (int idx = tid * 4; idx < 16384; idx += 1024) {
            int jl = idx >> 8, k = idx & 255;
            *(float4*)(whs + jl * 260 + k) =
                *(const float4*)(g_Wh + (size_t)(bn + j0 + jl) * 256 + k);
        }
        __syncthreads();

        // --- online softmax for this tile (4 threads per row) ---
        float mloc = -1e30f;
        #pragma unroll
        for (int jj = 0; jj < 16; jj++)
            mloc = fmaxf(mloc, sp[row * 68 + q * 16 + jj]);
        mloc = fmaxf(mloc, __shfl_xor_sync(0xffffffffu, mloc, 1));
        mloc = fmaxf(mloc, __shfl_xor_sync(0xffffffffu, mloc, 2));
        float m_old = m_s[row];
        float m_new = fmaxf(m_old, mloc);
        float ssum = 0.f;
        #pragma unroll
        for (int jj = 0; jj < 16; jj++) {
            float p = __expf(sp[row * 68 + q * 16 + jj] - m_new);
            sp[row * 68 + q * 16 + jj] = p;
            ssum += p;
        }
        ssum += __shfl_xor_sync(0xffffffffu, ssum, 1);
        ssum += __shfl_xor_sync(0xffffffffu, ssum, 2);
        if (q == 0) {
            float scale = __expf(m_old - m_new);
            l_s[row] = l_s[row] * scale + ssum;
            m_s[row] = m_new;
            sc_s[row] = scale;
        }
        __syncthreads();

        // --- rescale accumulators ---
        #pragma unroll
        for (int r = 0; r < 4; r++) {
            float sc = sc_s[ty * 4 + r];
            #pragma unroll
            for (int c = 0; c < 16; c++) acc[r][c] *= sc;
        }
        // --- accumulate p @ Wh ---
        #pragma unroll 2
        for (int jl = 0; jl < 64; jl++) {
            float pr[4];
            #pragma unroll
            for (int r = 0; r < 4; r++) pr[r] = sp[(ty * 4 + r) * 68 + jl];
            #pragma unroll
            for (int c4 = 0; c4 < 16; c4 += 4) {
                float4 w = *(float4*)(whs + jl * 260 + tx * 16 + c4);
                #pragma unroll
                for (int r = 0; r < 4; r++) {
                    acc[r][c4 + 0] += pr[r] * w.x;
                    acc[r][c4 + 1] += pr[r] * w.y;
                    acc[r][c4 + 2] += pr[r] * w.z;
                    acc[r][c4 + 3] += pr[r] * w.w;
                }
            }
        }
        __syncthreads();
    }

    // normalize by l
    #pragma unroll
    for (int r = 0; r < 4; r++) {
        float inv = 1.f / l_s[ty * 4 + r];
        #pragma unroll
        for (int c = 0; c < 16; c++) acc[r][c] *= inv;
    }
    // stash hp tile into whs (reuse)
    #pragma unroll
    for (int r = 0; r < 4; r++)
        #pragma unroll
        for (int c = 0; c < 16; c++)
            whs[(ty * 4 + r) * 260 + tx * 16 + c] = acc[r][c];
    __syncthreads();

    // output projection (256 -> 64) + elu. Thread: 4 rows x 4 out cols.
    float acc2[4][4];
    #pragma unroll
    for (int r = 0; r < 4; r++)
        #pragma unroll
        for (int c = 0; c < 4; c++) acc2[r][c] = 0.f;

    #pragma unroll 2
    for (int k = 0; k < 256; k++) {
        float4 wp = *(const float4*)(Wproj + k * 64 + tx * 4);
        #pragma unroll
        for (int r = 0; r < 4; r++) {
            float hv = whs[(ty * 4 + r) * 260 + k];
            acc2[r][0] += hv * wp.x;
            acc2[r][1] += hv * wp.y;
            acc2[r][2] += hv * wp.z;
            acc2[r][3] += hv * wp.w;
        }
    }
    #pragma unroll
    for (int r = 0; r < 4; r++) {
        int i = i0 + ty * 4 + r;
        float4 o;
        o.x = acc2[r][0] > 0.f ? acc2[r][0] : expm1f(acc2[r][0]);
        o.y = acc2[r][1] > 0.f ? acc2[r][1] : expm1f(acc2[r][1]);
        o.z = acc2[r][2] > 0.f ? acc2[r][2] : expm1f(acc2[r][2]);
        o.w = acc2[r][3] > 0.f ? acc2[r][3] : expm1f(acc2[r][3]);
        *(float4*)(out + (size_t)(bn + i) * 64 + tx * 4) = o;
    }
}

// ---------------------------------------------------------------------------
// Launch
// ---------------------------------------------------------------------------
extern "C" void kernel_launch(void* const* d_in, const int* in_sizes, int n_in,
                              void* d_out, int out_size)
{
    const float* h    = (const float*)d_in[0];
    const float* P    = (const float*)d_in[1];
    const float* Sim  = (const float*)d_in[2];
    const float* W    = (const float*)d_in[3];
    const float* Rp   = (const float*)d_in[4];
    const float* a_q  = (const float*)d_in[5];
    const float* a_k  = (const float*)d_in[6];
    const float* qb   = (const float*)d_in[7];
    const float* Wout = (const float*)d_in[8];
    const int*   qm   = (const int*)d_in[9];
    float* out = (float*)d_out;

    const int smemA = (128 * 64  + 64 * 132) * 4;   // 66560
    const int smemB = (128 * 128 + 64 * 132) * 4;   // 99328
    const int smemC = (128 * 256 + 64 * 132) * 4;   // 164864
    const int smemE = (64 * 68 + 64 * 260 + 192) * 4; // 84736

    cudaFuncSetAttribute(rowgemm_kernel<64, 0>,
                         cudaFuncAttributeMaxDynamicSharedMemorySize, smemA);
    cudaFuncSetAttribute(rowgemm_kernel<128, 1>,
                         cudaFuncAttributeMaxDynamicSharedMemorySize, smemB);
    cudaFuncSetAttribute(rowgemm_kernel<256, 2>,
                         cudaFuncAttributeMaxDynamicSharedMemorySize, smemC);
    cudaFuncSetAttribute(attn_kernel,
                         cudaFuncAttributeMaxDynamicSharedMemorySize, smemE);

    rowgemm_kernel<64, 0><<<128, 256, smemA>>>(h, Rp, nullptr);       // phi
    rowgemm_kernel<128, 1><<<128, 256, smemB>>>(nullptr, a_q, a_k);   // Q, K
    rowgemm_kernel<256, 2><<<128, 256, smemC>>>(h, W, nullptr);       // Wh
    scores_kernel<<<dim3(32, 32, 4), 256>>>(P, Sim, qm, qb);          // g_S
    attn_kernel<<<dim3(32, 4), 256, smemE>>>(Wout, out);              // out
}

// round 16
// speedup vs baseline: 1.0130x; 1.0130x over previous
#include <cuda_runtime.h>
#include <math.h>

// Problem constants
#define Bc   4
#define Nc   2048
#define INc  128
#define OUTc 64
#define Hc   4
#define HKc  256   // H * OUT

// ---------------------------------------------------------------------------
// Scratch (device globals — allocation-free rule)
// ---------------------------------------------------------------------------
__device__ float g_phi[Bc * Nc * 128];           //  4 MB  [row][128] cos|sin
__device__ float g_Q  [Bc * Nc * 64];            //  2 MB
__device__ float g_K  [Bc * Nc * 64];            //  2 MB
__device__ float g_Wh [Bc * Nc * 256];           //  8 MB
__device__ float g_S  [(size_t)Bc * Nc * Nc];    // 64 MB  pre-softmax scores

// ---------------------------------------------------------------------------
// Kernel 1 family: row GEMMs  Y(8192 x OUTW) = X(8192 x 128) @ W(128 x OUTW)
// MODE 0: X=h,   W=random_projection (OUTW=64)  -> g_phi = [cos, sin]
// MODE 1: X=g_phi, W=[a_q | a_k]     (OUTW=128) -> g_Q, g_K
// MODE 2: X=h,   W=W                 (OUTW=256) -> g_Wh
// 256 threads: ty=t/16 -> 4 rows, tx=t%16 -> OUTW/16 cols. Weights + X in smem.
// ---------------------------------------------------------------------------
template<int OUTW, int MODE>
__global__ __launch_bounds__(256)
void rowgemm_kernel(const float* __restrict__ X,
                    const float* __restrict__ W0,
                    const float* __restrict__ W1)
{
    constexpr int CW = OUTW / 16;
    extern __shared__ float smem[];
    float* Ws = smem;                 // 128 * OUTW
    float* Xs = smem + 128 * OUTW;    // 64 * 132 (padded)

    const int tid  = threadIdx.x;
    const int row0 = blockIdx.x * 64;

    // Stage weights
    if constexpr (MODE == 1) {
        for (int idx = tid * 4; idx < 128 * 64; idx += 1024) {
            int d = idx >> 6, o = idx & 63;
            *(float4*)(Ws + d * 128 + o)      = *(const float4*)(W0 + idx);
            *(float4*)(Ws + d * 128 + 64 + o) = *(const float4*)(W1 + idx);
        }
    } else {
        for (int idx = tid * 4; idx < 128 * OUTW; idx += 1024)
            *(float4*)(Ws + idx) = *(const float4*)(W0 + idx);
    }
    // Stage X tile (64 x 128, padded stride 132)
    const float* Xp = (MODE == 1) ? (const float*)g_phi : X;
    for (int idx = tid * 4; idx < 64 * 128; idx += 1024) {
        int rl = idx >> 7, d = idx & 127;
        *(float4*)(Xs + rl * 132 + d) =
            *(const float4*)(Xp + (size_t)(row0 + rl) * 128 + d);
    }
    __syncthreads();

    const int ty = tid >> 4, tx = tid & 15;
    float acc[4][CW];
    #pragma unroll
    for (int r = 0; r < 4; r++)
        #pragma unroll
        for (int c = 0; c < CW; c++) acc[r][c] = 0.f;

    for (int d = 0; d < 128; d++) {
        float xv[4];
        #pragma unroll
        for (int r = 0; r < 4; r++) xv[r] = Xs[(ty * 4 + r) * 132 + d];
        #pragma unroll
        for (int c4 = 0; c4 < CW; c4 += 4) {
            float4 w = *(float4*)(Ws + d * OUTW + tx * CW + c4);
            #pragma unroll
            for (int r = 0; r < 4; r++) {
                acc[r][c4 + 0] += xv[r] * w.x;
                acc[r][c4 + 1] += xv[r] * w.y;
                acc[r][c4 + 2] += xv[r] * w.z;
                acc[r][c4 + 3] += xv[r] * w.w;
            }
        }
    }

    #pragma unroll
    for (int r = 0; r < 4; r++) {
        int row = row0 + ty * 4 + r;
        if constexpr (MODE == 0) {
            // phi = [cos(proj), sin(proj)]
            float4 cv = make_float4(cosf(acc[r][0]), cosf(acc[r][1]),
                                    cosf(acc[r][2]), cosf(acc[r][3]));
            float4 sv = make_float4(sinf(acc[r][0]), sinf(acc[r][1]),
                                    sinf(acc[r][2]), sinf(acc[r][3]));
            *(float4*)(g_phi + (size_t)row * 128 + tx * 4)      = cv;
            *(float4*)(g_phi + (size_t)row * 128 + 64 + tx * 4) = sv;
        } else if constexpr (MODE == 1) {
            #pragma unroll
            for (int c4 = 0; c4 < CW; c4 += 4) {
                float4 v = make_float4(acc[r][c4], acc[r][c4 + 1],
                                       acc[r][c4 + 2], acc[r][c4 + 3]);
                int o = tx * CW + c4;
                if (o < 64) *(float4*)(g_Q + (size_t)row * 64 + o)        = v;
                else        *(float4*)(g_K + (size_t)row * 64 + (o - 64)) = v;
            }
        } else {
            #pragma unroll
            for (int c4 = 0; c4 < CW; c4 += 4) {
                float4 v = make_float4(acc[r][c4], acc[r][c4 + 1],
                                       acc[r][c4 + 2], acc[r][c4 + 3]);
                *(float4*)(g_Wh + (size_t)row * 256 + tx * CW + c4) = v;
            }
        }
    }
}

// ---------------------------------------------------------------------------
// Kernel 2: pre-softmax scores
//   g_S[b,i,j] = Q[b,i]·K[b,j] + P[b,i,j] + Sim[b,i,j] + qbias[qm0, qm1]
// CTA tile 64i x 64j, thread tile 4x4. Memory-bound (streams P/Sim/qm).
// ---------------------------------------------------------------------------
__global__ __launch_bounds__(256)
void scores_kernel(const float* __restrict__ P, const float* __restrict__ Sim,
                   const int* __restrict__ qm, const float* __restrict__ qbias)
{
    __shared__ float Qs[64 * 65];
    __shared__ float Kst[64 * 65];   // transposed: [d][jl]
    __shared__ float qbs[16];

    const int b = blockIdx.z, i0 = blockIdx.y * 64, j0 = blockIdx.x * 64;
    const int tid = threadIdx.x;
    const int bn = b * Nc;

    if (tid < 16) qbs[tid] = qbias[tid];
    for (int idx = tid; idx < 4096; idx += 256) {
        int il = idx >> 6, d = idx & 63;
        Qs[il * 65 + d] = g_Q[(size_t)(bn + i0 + il) * 64 + d];
    }
    for (int idx = tid; idx < 4096; idx += 256) {
        int jl = idx >> 6, d = idx & 63;
        Kst[d * 65 + jl] = g_K[(size_t)(bn + j0 + jl) * 64 + d];
    }
    __syncthreads();

    const int ty = tid >> 4, tx = tid & 15;
    float acc[4][4];
    #pragma unroll
    for (int r = 0; r < 4; r++)
        #pragma unroll
        for (int c = 0; c < 4; c++) acc[r][c] = 0.f;

    #pragma unroll 4
    for (int d = 0; d < 64; d++) {
        float qv[4], kv[4];
        #pragma unroll
        for (int r = 0; r < 4; r++) qv[r] = Qs[(ty * 4 + r) * 65 + d];
        #pragma unroll
        for (int c = 0; c < 4; c++) kv[c] = Kst[d * 65 + tx * 4 + c];
        #pragma unroll
        for (int r = 0; r < 4; r++)
            #pragma unroll
            for (int c = 0; c < 4; c++) acc[r][c] += qv[r] * kv[c];
    }

    #pragma unroll
    for (int r = 0; r < 4; r++) {
        int i = i0 + ty * 4 + r;
        size_t gi = (size_t)(bn + i) * Nc + j0 + tx * 4;
        float4 p4 = *(const float4*)(P + gi);
        float4 s4 = *(const float4*)(Sim + gi);
        int4 qa = *(const int4*)(qm + gi * 2);
        int4 qb = *(const int4*)(qm + gi * 2 + 4);
        float4 o;
        o.x = acc[r][0] + p4.x + s4.x + qbs[qa.x * 4 + qa.y];
        o.y = acc[r][1] + p4.y + s4.y + qbs[qa.z * 4 + qa.w];
        o.z = acc[r][2] + p4.z + s4.z + qbs[qb.x * 4 + qb.y];
        o.w = acc[r][3] + p4.w + s4.w + qbs[qb.z * 4 + qb.w];
        *(float4*)(g_S + gi) = o;
    }
}

// ---------------------------------------------------------------------------
// Kernel 3: fused online-softmax + attn@Wh + output projection + elu
// One CTA per (b, 64-query tile). 256 threads: ty=t/16 -> 4 rows,
// tx=t%16 -> 16 of 256 hp columns (acc[4][16] registers).
// Softmax phase uses (row = t/4, q = t%4) with intra-quad shuffles.
// ---------------------------------------------------------------------------
__global__ __launch_bounds__(256)
void attn_kernel(const float* __restrict__ Wproj, float* __restrict__ out)
{
    extern __shared__ float smem[];
    float* sp   = smem;                 // 64 * 68  (scores -> probs)
    float* whs  = smem + 64 * 68;       // 64 * 260 (Wh tile, later hp tile)
    float* m_s  = whs + 64 * 260;       // 64
    float* l_s  = m_s + 64;             // 64
    float* sc_s = l_s + 64;             // 64

    const int b  = blockIdx.y;
    const int i0 = blockIdx.x * 64;
    const int tid = threadIdx.x;
    const int ty = tid >> 4, tx = tid & 15;
    const int row = tid >> 2, q = tid & 3;
    const int bn = b * Nc;

    float acc[4][16];
    #pragma unroll
    for (int r = 0; r < 4; r++)
        #pragma unroll
        for (int c = 0; c < 16; c++) acc[r][c] = 0.f;

    if (tid < 64) { m_s[tid] = -1e30f; l_s[tid] = 0.f; }

    for (int jt = 0; jt < 32; jt++) {
        const int j0 = jt * 64;
        // load score tile (64 x 64)
        for (int idx = tid * 4; idx < 4096; idx += 1024) {
            int il = idx >> 6, jl = idx & 63;
            *(float4*)(sp + il * 68 + jl) =
                *(const float4*)(g_S + (size_t)(bn + i0 + il) * Nc + j0 + jl);
        }
        // load Wh tile (64 x 256)
        for (int idx = tid * 4; idx < 16384; idx += 1024) {
            int jl = idx >> 8, k = idx & 255;
            *(float4*)(whs + jl * 260 + k) =
                *(const float4*)(g_Wh + (size_t)(bn + j0 + jl) * 256 + k);
        }
        __syncthreads();

        // --- online softmax for this tile (4 threads per row) ---
        float mloc = -1e30f;
        #pragma unroll
        for (int jj = 0; jj < 16; jj++)
            mloc = fmaxf(mloc, sp[row * 68 + q * 16 + jj]);
        mloc = fmaxf(mloc, __shfl_xor_sync(0xffffffffu, mloc, 1));
        mloc = fmaxf(mloc, __shfl_xor_sync(0xffffffffu, mloc, 2));
        float m_old = m_s[row];
        float m_new = fmaxf(m_old, mloc);
        float ssum = 0.f;
        #pragma unroll
        for (int jj = 0; jj < 16; jj++) {
            float p = __expf(sp[row * 68 + q * 16 + jj] - m_new);
            sp[row * 68 + q * 16 + jj] = p;
            ssum += p;
        }
        ssum += __shfl_xor_sync(0xffffffffu, ssum, 1);
        ssum += __shfl_xor_sync(0xffffffffu, ssum, 2);
        if (q == 0) {
            float scale = __expf(m_old - m_new);
            l_s[row] = l_s[row] * scale + ssum;
            m_s[row] = m_new;
            sc_s[row] = scale;
        }
        __syncthreads();

        // --- rescale accumulators ---
        #pragma unroll
        for (int r = 0; r < 4; r++) {
            float sc = sc_s[ty * 4 + r];
            #pragma unroll
            for (int c = 0; c < 16; c++) acc[r][c] *= sc;
        }
        // --- accumulate p @ Wh ---
        #pragma unroll 2
        for (int jl = 0; jl < 64; jl++) {
            float pr[4];
            #pragma unroll
            for (int r = 0; r < 4; r++) pr[r] = sp[(ty * 4 + r) * 68 + jl];
            #pragma unroll
            for (int c4 = 0; c4 < 16; c4 += 4) {
                float4 w = *(float4*)(whs + jl * 260 + tx * 16 + c4);
                #pragma unroll
                for (int r = 0; r < 4; r++) {
                    acc[r][c4 + 0] += pr[r] * w.x;
                    acc[r][c4 + 1] += pr[r] * w.y;
                    acc[r][c4 + 2] += pr[r] * w.z;
                    acc[r][c4 + 3] += pr[r] * w.w;
                }
            }
        }
        __syncthreads();
    }

    // normalize by l
    #pragma unroll
    for (int r = 0; r < 4; r++) {
        float inv = 1.f / l_s[ty * 4 + r];
        #pragma unroll
        for (int c = 0; c < 16; c++) acc[r][c] *= inv;
    }
    // stash hp tile into whs (reuse)
    #pragma unroll
    for (int r = 0; r < 4; r++)
        #pragma unroll
        for (int c = 0; c < 16; c++)
            whs[(ty * 4 + r) * 260 + tx * 16 + c] = acc[r][c];
    __syncthreads();

    // output projection (256 -> 64) + elu. Thread: 4 rows x 4 out cols.
    float acc2[4][4];
    #pragma unroll
    for (int r = 0; r < 4; r++)
        #pragma unroll
        for (int c = 0; c < 4; c++) acc2[r][c] = 0.f;

    #pragma unroll 2
    for (int k = 0; k < 256; k++) {
        float4 wp = *(const float4*)(Wproj + k * 64 + tx * 4);
        #pragma unroll
        for (int r = 0; r < 4; r++) {
            float hv = whs[(ty * 4 + r) * 260 + k];
            acc2[r][0] += hv * wp.x;
            acc2[r][1] += hv * wp.y;
            acc2[r][2] += hv * wp.z;
            acc2[r][3] += hv * wp.w;
        }
    }
    #pragma unroll
    for (int r = 0; r < 4; r++) {
        int i = i0 + ty * 4 + r;
        float4 o;
        o.x = acc2[r][0] > 0.f ? acc2[r][0] : expm1f(acc2[r][0]);
        o.y = acc2[r][1] > 0.f ? acc2[r][1] : expm1f(acc2[r][1]);
        o.z = acc2[r][2] > 0.f ? acc2[r][2] : expm1f(acc2[r][2]);
        o.w = acc2[r][3] > 0.f ? acc2[r][3] : expm1f(acc2[r][3]);
        *(float4*)(out + (size_t)(bn + i) * 64 + tx * 4) = o;
    }
}

// ---------------------------------------------------------------------------
// Launch
// ---------------------------------------------------------------------------
extern "C" void kernel_launch(void* const* d_in, const int* in_sizes, int n_in,
                              void* d_out, int out_size)
{
    const float* h    = (const float*)d_in[0];
    const float* P    = (const float*)d_in[1];
    const float* Sim  = (const float*)d_in[2];
    const float* W    = (const float*)d_in[3];
    const float* Rp   = (const float*)d_in[4];
    const float* a_q  = (const float*)d_in[5];
    const float* a_k  = (const float*)d_in[6];
    const float* qb   = (const float*)d_in[7];
    const float* Wout = (const float*)d_in[8];
    const int*   qm   = (const int*)d_in[9];
    float* out = (float*)d_out;

    const int smemA = (128 * 64  + 64 * 132) * 4;   // 66560
    const int smemB = (128 * 128 + 64 * 132) * 4;   // 99328
    const int smemC = (128 * 256 + 64 * 132) * 4;   // 164864
    const int smemE = (64 * 68 + 64 * 260 + 192) * 4; // 84736

    cudaFuncSetAttribute(rowgemm_kernel<64, 0>,
                         cudaFuncAttributeMaxDynamicSharedMemorySize, smemA);
    cudaFuncSetAttribute(rowgemm_kernel<128, 1>,
                         cudaFuncAttributeMaxDynamicSharedMemorySize, smemB);
    cudaFuncSetAttribute(rowgemm_kernel<256, 2>,
                         cudaFuncAttributeMaxDynamicSharedMemorySize, smemC);
    cudaFuncSetAttribute(attn_kernel,
                         cudaFuncAttributeMaxDynamicSharedMemorySize, smemE);

    rowgemm_kernel<64, 0><<<128, 256, smemA>>>(h, Rp, nullptr);       // phi
    rowgemm_kernel<128, 1><<<128, 256, smemB>>>(nullptr, a_q, a_k);   // Q, K
    rowgemm_kernel<256, 2><<<128, 256, smemC>>>(h, W, nullptr);       // Wh
    scores_kernel<<<dim3(32, 32, 4), 256>>>(P, Sim, qm, qb);          // g_S
    attn_kernel<<<dim3(32, 4), 256, smemE>>>(Wout, out);              // out
}